// round 1
// baseline (speedup 1.0000x reference)
#include <cuda_runtime.h>
#include <cuda_bf16.h>

// Problem constants (fixed by the reference): N=512, B=256, F=400, D=14, K=2
#define NN 512
#define BB 256
#define FF 400
#define DD 14
#define KK 2
#define PIX (DD * DD)            // 196 pixels per (b,f)
#define NWARPS_TOTAL (BB * FF)   // one warp per (b,f) pair = 102400 warps

// One warp handles one (b,f):
//   phase A: lanes 0..27 build separable Gaussian tables (x: lanes 0-13, y: lanes 14-27)
//            for both spots; coefficient mask*h/(2*pi*w^2) folded into the x entries.
//   phase B: 7 strided iterations over 196 pixels; value via 4 SHFL.IDX + FMA chain.
__global__ __launch_bounds__(256) void gaussian_spot_kernel(
    const int*          __restrict__ batch_idx,   // (B,)
    const unsigned int* __restrict__ m_mask,      // (B,F,K) as 32-bit words; nonzero == true
    const float*        __restrict__ height,      // (B,F,K)
    const float*        __restrict__ width,       // (B,F,K)
    const float*        __restrict__ x0,          // (B,F,K)
    const float*        __restrict__ y0,          // (B,F,K)
    const float*        __restrict__ background,  // (B,F)
    const float*        __restrict__ target_locs, // (N,F,2)
    float*              __restrict__ out)         // (B,F,D,D)
{
    const int warp_global = (blockIdx.x * blockDim.x + threadIdx.x) >> 5;
    const int lane = threadIdx.x & 31;
    if (warp_global >= NWARPS_TOTAL) return;

    const int bf = warp_global;
    const int b  = bf / FF;
    const int f  = bf - b * FF;

    // ---- per-(b,f) parameters (warp-uniform loads; L1/L2 broadcast) ----
    const int   n   = batch_idx[b];
    const float tlx = target_locs[(n * FF + f) * 2 + 0];
    const float tly = target_locs[(n * FF + f) * 2 + 1];
    const float bg  = background[bf];

    const int base = bf * KK;

    // spot 0
    const float h0   = (m_mask[base + 0] != 0u) ? height[base + 0] : 0.0f;
    const float w0   = width[base + 0];
    const float cx0  = tlx + x0[base + 0];
    const float cy0  = tly + y0[base + 0];
    const float iw20 = __fdividef(1.0f, w0 * w0);
    const float a0   = -0.5f * iw20;
    const float c0   = h0 * iw20 * 0.15915494309189533577f;   // 1/(2*pi)

    // spot 1
    const float h1   = (m_mask[base + 1] != 0u) ? height[base + 1] : 0.0f;
    const float w1   = width[base + 1];
    const float cx1  = tlx + x0[base + 1];
    const float cy1  = tly + y0[base + 1];
    const float iw21 = __fdividef(1.0f, w1 * w1);
    const float a1   = -0.5f * iw21;
    const float c1   = h1 * iw21 * 0.15915494309189533577f;

    // ---- phase A: separable tables in registers (indexed via SHFL) ----
    // lane l < 14  : x-axis entry for pixel row i=l        (coefficient folded in)
    // 14 <= l < 28 : y-axis entry for pixel col j=l-14
    const bool  isx = (lane < DD);
    const float pos = (float)(isx ? lane : lane - DD);
    const float d0  = pos - (isx ? cx0 : cy0);
    const float d1  = pos - (isx ? cx1 : cy1);
    const float e0  = __expf(a0 * d0 * d0);
    const float e1  = __expf(a1 * d1 * d1);
    const float t0  = isx ? c0 * e0 : e0;
    const float t1  = isx ? c1 * e1 : e1;

    // ---- phase B: 196 pixels, 32 lanes, 7 iterations ----
    float* o = out + (size_t)bf * PIX;
#pragma unroll
    for (int it = 0; it < 7; ++it) {
        const int p = lane + it * 32;            // pixel index, < 224
        const unsigned i = (unsigned)p / 14u;    // row  (const-div -> mul/shift)
        const unsigned j = (unsigned)p - i * 14u;
        // all lanes participate in shuffles (lane indices stay < 32)
        const float xa = __shfl_sync(0xffffffffu, t0, (int)i);
        const float ya = __shfl_sync(0xffffffffu, t0, (int)(14u + j));
        const float xb = __shfl_sync(0xffffffffu, t1, (int)i);
        const float yb = __shfl_sync(0xffffffffu, t1, (int)(14u + j));
        const float v  = fmaf(xa, ya, fmaf(xb, yb, bg));
        if (p < PIX) o[p] = v;
    }
}

extern "C" void kernel_launch(void* const* d_in, const int* in_sizes, int n_in,
                              void* d_out, int out_size) {
    (void)in_sizes; (void)n_in; (void)out_size;
    const int*          batch_idx   = (const int*)d_in[0];
    const unsigned int* m_mask      = (const unsigned int*)d_in[1];
    const float*        height      = (const float*)d_in[2];
    const float*        width       = (const float*)d_in[3];
    const float*        x0          = (const float*)d_in[4];
    const float*        y0          = (const float*)d_in[5];
    const float*        background  = (const float*)d_in[6];
    const float*        target_locs = (const float*)d_in[7];
    // d_in[8] = pixel_pos (meshgrid) — implicit in the kernel, unused.
    float* out = (float*)d_out;

    const int threads = 256;                       // 8 warps/block, 1 (b,f) per warp
    const int total_threads = NWARPS_TOTAL * 32;   // 102400 warps
    const int blocks = (total_threads + threads - 1) / threads;  // 12800
    gaussian_spot_kernel<<<blocks, threads>>>(batch_idx, m_mask, height, width,
                                              x0, y0, background, target_locs, out);
}

// round 2
// speedup vs baseline: 1.4977x; 1.4977x over previous
#include <cuda_runtime.h>
#include <cuda_bf16.h>

// Problem constants (fixed by the reference): N=512, B=256, F=400, D=14, K=2
#define NN 512
#define BB 256
#define FF 400
#define DD 14
#define KK 2
#define PIX (DD * DD)                 // 196 pixels per (b,f)
#define NTILES (BB * FF)              // 102400 (b,f) tiles
#define NWARPS (NTILES / 2)           // 2 tiles per warp -> 51200 warps
#define LOG2E 1.4426950408889634074f
#define INV2PI 0.15915494309189533577f

// Warp layout: lanes 0-15 -> tile (2w), lanes 16-31 -> tile (2w+1).
//   sub = lane & 15.  Lane `sub` holds:
//     x-table entry for row index `sub` (coeff mask*h/(2*pi*w^2) folded in), both spots
//     y-table entries for columns j0=2*(sub%7), j0+1 (no coeff), both spots
//   Phase B: 7 iterations; iteration `it` covers rows 2*it and 2*it+1:
//     lanes with sub<7 take row 2*it, sub in [7,14) take row 2*it+1.
//     Per iter: 2 SHFL (x entries, one per spot; single instruction serves
//     both half-warps via computed source lane) + 4 FMA + 1 STG.64.
__global__ __launch_bounds__(256) void gaussian_spot_kernel(
    const int*          __restrict__ batch_idx,   // (B,)
    const uint2*        __restrict__ m_mask,      // (B,F,K) 32-bit words; nonzero == true
    const float2*       __restrict__ height,      // (B,F,K)
    const float2*       __restrict__ width,       // (B,F,K)
    const float2*       __restrict__ x0,          // (B,F,K)
    const float2*       __restrict__ y0,          // (B,F,K)
    const float*        __restrict__ background,  // (B,F)
    const float2*       __restrict__ target_locs, // (N,F,2)
    float*              __restrict__ out)         // (B,F,D,D)
{
    const int warp  = (blockIdx.x * blockDim.x + threadIdx.x) >> 5;
    const int lane  = threadIdx.x & 31;
    const int sub   = lane & 15;
    const int half  = lane >> 4;

    const int bf = warp * 2 + half;            // this lane's tile (grid is exact)
    const int b  = bf / FF;
    const int f  = bf - b * FF;

    // ---- per-tile parameters (uniform within each half-warp) ----
    const int    n   = batch_idx[b];
    const float2 tl  = target_locs[n * FF + f];
    const float  bg  = background[bf];

    const uint2  mm = m_mask[bf];
    const float2 hh = height[bf];
    const float2 ww = width[bf];
    const float2 xx = x0[bf];
    const float2 yy = y0[bf];

    // spot 0
    const float h0   = (mm.x != 0u) ? hh.x : 0.0f;
    const float iw20 = __fdividef(1.0f, ww.x * ww.x);
    const float a0   = -0.5f * LOG2E * iw20;          // exp2-scaled
    const float c0   = h0 * iw20 * INV2PI;
    const float cx0  = tl.x + xx.x;
    const float cy0  = tl.y + yy.x;
    // spot 1
    const float h1   = (mm.y != 0u) ? hh.y : 0.0f;
    const float iw21 = __fdividef(1.0f, ww.y * ww.y);
    const float a1   = -0.5f * LOG2E * iw21;
    const float c1   = h1 * iw21 * INV2PI;
    const float cx1  = tl.x + xx.y;
    const float cy1  = tl.y + yy.y;

    // ---- phase A: per-lane table entries (6 exp2 per lane) ----
    const int  r2  = (sub >= 7) ? 1 : 0;       // row parity within the 2-row group
    const int  s7  = sub - 7 * r2;             // column-pair index 0..6 (lanes 14,15 alias 7,8)
    // x entry for row `sub` (coeff folded in)
    const float dx0 = (float)sub - cx0;
    const float dx1 = (float)sub - cx1;
    const float xr0 = c0 * exp2f(a0 * dx0 * dx0);
    const float xr1 = c1 * exp2f(a1 * dx1 * dx1);
    // y entries for columns 2*s7, 2*s7+1
    const float py0 = (float)(2 * s7);
    const float py1 = py0 + 1.0f;
    const float d00 = py0 - cy0, d01 = py1 - cy0;
    const float d10 = py0 - cy1, d11 = py1 - cy1;
    const float ya_e = exp2f(a0 * d00 * d00);
    const float ya_o = exp2f(a0 * d01 * d01);
    const float yb_e = exp2f(a1 * d10 * d10);
    const float yb_o = exp2f(a1 * d11 * d11);

    // ---- phase B: 7 iterations x (2 rows, float2 columns) ----
    const int sbase = (lane & 16) + r2;        // shuffle source base (row 0/1 of group, own half)
    // per-lane output pointer: element (row=r2, col=2*s7) of tile bf
    float2* o = (float2*)(out + (size_t)bf * PIX + r2 * DD + 2 * s7);
    const bool active = (sub < DD);            // lanes 14,15 duplicate 7,8 -> masked

#pragma unroll
    for (int it = 0; it < 7; ++it) {
        const int src = sbase + 2 * it;
        const float xa = __shfl_sync(0xffffffffu, xr0, src);
        const float xb = __shfl_sync(0xffffffffu, xr1, src);
        float2 v;
        v.x = fmaf(xa, ya_e, fmaf(xb, yb_e, bg));
        v.y = fmaf(xa, ya_o, fmaf(xb, yb_o, bg));
        if (active) o[it * DD] = v;            // advance 2 rows = 14 float2
    }
}

extern "C" void kernel_launch(void* const* d_in, const int* in_sizes, int n_in,
                              void* d_out, int out_size) {
    (void)in_sizes; (void)n_in; (void)out_size;
    const int*    batch_idx   = (const int*)d_in[0];
    const uint2*  m_mask      = (const uint2*)d_in[1];
    const float2* height      = (const float2*)d_in[2];
    const float2* width       = (const float2*)d_in[3];
    const float2* x0          = (const float2*)d_in[4];
    const float2* y0          = (const float2*)d_in[5];
    const float*  background  = (const float*)d_in[6];
    const float2* target_locs = (const float2*)d_in[7];
    // d_in[8] = pixel_pos (meshgrid) — implicit in the kernel, unused.
    float* out = (float*)d_out;

    const int threads = 256;                      // 8 warps/block, 16 tiles/block
    const int blocks  = (NWARPS * 32) / threads;  // 6400, exact
    gaussian_spot_kernel<<<blocks, threads>>>(batch_idx, m_mask, height, width,
                                              x0, y0, background, target_locs, out);
}

// round 3
// speedup vs baseline: 1.6580x; 1.1071x over previous
#include <cuda_runtime.h>
#include <cuda_bf16.h>

// Problem constants (fixed by the reference): N=512, B=256, F=400, D=14, K=2
#define NN 512
#define BB 256
#define FF 400
#define DD 14
#define KK 2
#define PIX (DD * DD)                 // 196 pixels per (b,f)
#define NTILES (BB * FF)              // 102400 (b,f) tiles
#define NWARPS (NTILES / 2)           // 2 tiles per warp -> 51200 warps
#define LOG2E 1.4426950408889634074f
#define INV2PI 0.15915494309189533577f

// Guaranteed single-MUFU ops regardless of harness compile flags.
__device__ __forceinline__ float ex2f_fast(float x) {
    float r; asm("ex2.approx.ftz.f32 %0, %1;" : "=f"(r) : "f"(x)); return r;
}
__device__ __forceinline__ float rcpf_fast(float x) {
    float r; asm("rcp.approx.ftz.f32 %0, %1;" : "=f"(r) : "f"(x)); return r;
}

// Warp layout: lanes 0-15 -> tile (2w), lanes 16-31 -> tile (2w+1).
//   sub = lane & 15.  Lane `sub` holds:
//     x-table entry for row index `sub` (coeff mask*h/(2*pi*w^2) folded in), both spots
//     y-table entries for columns j0=2*(sub%7), j0+1 (no coeff), both spots
//   Phase B: 7 iterations; iteration `it` covers rows 2*it and 2*it+1:
//     lanes with sub<7 take row 2*it, sub in [7,14) take row 2*it+1.
//     Per iter: 2 SHFL + 4 FMA + 1 streaming STG.64.
__global__ __launch_bounds__(256) void gaussian_spot_kernel(
    const int*          __restrict__ batch_idx,   // (B,)
    const uint2*        __restrict__ m_mask,      // (B,F,K) 32-bit words; nonzero == true
    const float2*       __restrict__ height,      // (B,F,K)
    const float2*       __restrict__ width,       // (B,F,K)
    const float2*       __restrict__ x0,          // (B,F,K)
    const float2*       __restrict__ y0,          // (B,F,K)
    const float*        __restrict__ background,  // (B,F)
    const float2*       __restrict__ target_locs, // (N,F,2)
    float*              __restrict__ out)         // (B,F,D,D)
{
    const int warp  = (blockIdx.x * blockDim.x + threadIdx.x) >> 5;
    const int lane  = threadIdx.x & 31;
    const int sub   = lane & 15;
    const int half  = lane >> 4;

    const int bf = warp * 2 + half;            // this lane's tile (grid is exact)
    const int b  = bf / FF;
    const int f  = bf - b * FF;

    // ---- per-tile parameters (uniform within each half-warp) ----
    const int    n   = batch_idx[b];
    const float2 tl  = target_locs[n * FF + f];
    const float  bg  = background[bf];

    const uint2  mm = m_mask[bf];
    const float2 hh = height[bf];
    const float2 ww = width[bf];
    const float2 xx = x0[bf];
    const float2 yy = y0[bf];

    // spot 0
    const float h0   = (mm.x != 0u) ? hh.x : 0.0f;
    const float iw20 = rcpf_fast(ww.x * ww.x);
    const float a0   = (-0.5f * LOG2E) * iw20;        // exp2-scaled
    const float c0   = h0 * iw20 * INV2PI;
    const float cx0  = tl.x + xx.x;
    const float cy0  = tl.y + yy.x;
    // spot 1
    const float h1   = (mm.y != 0u) ? hh.y : 0.0f;
    const float iw21 = rcpf_fast(ww.y * ww.y);
    const float a1   = (-0.5f * LOG2E) * iw21;
    const float c1   = h1 * iw21 * INV2PI;
    const float cx1  = tl.x + xx.y;
    const float cy1  = tl.y + yy.y;

    // ---- phase A: per-lane table entries (6 EX2 per lane) ----
    const int  r2  = (sub >= 7) ? 1 : 0;       // row parity within the 2-row group
    const int  s7  = sub - 7 * r2;             // column-pair index 0..6 (lanes 14,15 alias 7,8)
    // x entry for row `sub` (coeff folded in)
    const float dx0 = (float)sub - cx0;
    const float dx1 = (float)sub - cx1;
    const float xr0 = c0 * ex2f_fast(a0 * dx0 * dx0);
    const float xr1 = c1 * ex2f_fast(a1 * dx1 * dx1);
    // y entries for columns 2*s7, 2*s7+1
    const float py0 = (float)(2 * s7);
    const float py1 = py0 + 1.0f;
    const float d00 = py0 - cy0, d01 = py1 - cy0;
    const float d10 = py0 - cy1, d11 = py1 - cy1;
    const float ya_e = ex2f_fast(a0 * d00 * d00);
    const float ya_o = ex2f_fast(a0 * d01 * d01);
    const float yb_e = ex2f_fast(a1 * d10 * d10);
    const float yb_o = ex2f_fast(a1 * d11 * d11);

    // ---- phase B: 7 iterations x (2 rows, float2 columns) ----
    const int sbase = (lane & 16) + r2;        // shuffle source base (row 0/1 of group, own half)
    // per-lane output pointer: element (row=r2, col=2*s7) of tile bf
    float2* o = (float2*)(out + (size_t)bf * PIX + r2 * DD + 2 * s7);
    const bool active = (sub < DD);            // lanes 14,15 duplicate 7,8 -> masked

#pragma unroll
    for (int it = 0; it < 7; ++it) {
        const int src = sbase + 2 * it;
        const float xa = __shfl_sync(0xffffffffu, xr0, src);
        const float xb = __shfl_sync(0xffffffffu, xr1, src);
        float2 v;
        v.x = fmaf(xa, ya_e, fmaf(xb, yb_e, bg));
        v.y = fmaf(xa, ya_o, fmaf(xb, yb_o, bg));
        if (active) __stcs(&o[it * DD], v);    // streaming store, advance 2 rows
    }
}

extern "C" void kernel_launch(void* const* d_in, const int* in_sizes, int n_in,
                              void* d_out, int out_size) {
    (void)in_sizes; (void)n_in; (void)out_size;
    const int*    batch_idx   = (const int*)d_in[0];
    const uint2*  m_mask      = (const uint2*)d_in[1];
    const float2* height      = (const float2*)d_in[2];
    const float2* width       = (const float2*)d_in[3];
    const float2* x0          = (const float2*)d_in[4];
    const float2* y0          = (const float2*)d_in[5];
    const float*  background  = (const float*)d_in[6];
    const float2* target_locs = (const float2*)d_in[7];
    // d_in[8] = pixel_pos (meshgrid) — implicit in the kernel, unused.
    float* out = (float*)d_out;

    const int threads = 256;                      // 8 warps/block, 16 tiles/block
    const int blocks  = (NWARPS * 32) / threads;  // 6400, exact
    gaussian_spot_kernel<<<blocks, threads>>>(batch_idx, m_mask, height, width,
                                              x0, y0, background, target_locs, out);
}